// round 12
// baseline (speedup 1.0000x reference)
#include <cuda_runtime.h>
#include <cuda_fp16.h>
#include <mma.h>
#include <cstddef>

using namespace nvcuda;

#define BATCH 256
#define HID   512
#define NBLK  128           // chain: 8 row-groups x 16 col-tiles
#define AS    520           // smem k-stride (elems): 1040B rows, LDSM conflict-free
#define RPAD  36            // chain reduction row stride (fp32)
#define MAXSTEP 256

// ---- scratch (static __device__, allocation-free per harness rules) ----
__device__ __half    g_E[32000 * HID];          // embedding, fp16
__device__ __half    g_Hh[2][BATCH * HID];      // ping-pong hidden, fp16 hi
__device__ __half    g_Hl[2][BATCH * HID];      // fp16 residual
__device__ float     g_P[(size_t)MAXSTEP * BATCH * HID];  // P[s-1] = E_s@Wr + b
__device__ unsigned  g_bar[8 * 32];             // per-row-group barrier counters

struct PSMem {                       // prelude block
    __half Wth[32][AS];              // Wr col-slice, k-major, hi (33280B)
    __half Wtl[32][AS];              // lo
    __half E[2][32][AS];             // double-buffered E tiles (66560B)
    float  red[8][16][20];           // 8 warp quadrants (10240B)
    int    stok[32];
};                                    // ~143.6KB

struct CSMem {                       // chain block
    __half Wth[32][AS];              // Wl col-slice, k-major, hi
    __half Wtl[32][AS];              // lo
    __half Hp[2][32][AS];            // H hi/lo staging, K=512 (66560B)
    float  red[8][32][RPAD];         // 8 warp partials (36864B)
    float  Pb[2][32][32];            // double-buffered P tiles (8192B)
};                                    // ~178.2KB

// tokens may be int32 (jax default) or int64. tokens[0][1] is a real token
// >= 3, so a zero second 32-bit word means little-endian int64.
__device__ __forceinline__ int load_tok(const int* tokens, long long idx)
{
    if (tokens[1] == 0) return (int)((const long long*)tokens)[idx];
    return tokens[idx];
}

__device__ __forceinline__ void split_h(float x, __half& hi, __half& lo)
{
    hi = __float2half_rn(x);
    lo = __float2half_rn(x - __half2float(hi));
}

__device__ __forceinline__ void cp_async16(void* dst, const void* src)
{
    unsigned d = (unsigned)__cvta_generic_to_shared(dst);
    asm volatile("cp.async.cg.shared.global [%0], [%1], 16;" :: "r"(d), "l"(src));
}
__device__ __forceinline__ void cp_commit()
{
    asm volatile("cp.async.commit_group;" ::: "memory");
}
template <int N> __device__ __forceinline__ void cp_wait()
{
    asm volatile("cp.async.wait_group %0;" :: "n"(N) : "memory");
}

__device__ __forceinline__ void bar_arrive(unsigned* p)
{
    asm volatile("red.release.gpu.global.add.u32 [%0], %1;"
                 :: "l"(p), "r"(1u) : "memory");
}
__device__ __forceinline__ unsigned bar_peek(const unsigned* p)
{
    unsigned v;
    asm volatile("ld.acquire.gpu.global.u32 %0, [%1];"
                 : "=r"(v) : "l"(p) : "memory");
    return v;
}

// ---- convert the embedding table to fp16 ----
__global__ void prep_emb(const float* __restrict__ emb, int n)
{
    int e = (blockIdx.x * blockDim.x + threadIdx.x) * 4;
    if (e >= n) return;
    float4 v = __ldcs((const float4*)(emb + e));
    __half2 p01 = __floats2half2_rn(v.x, v.y);
    __half2 p23 = __floats2half2_rn(v.z, v.w);
    __stcs((uint2*)&g_E[e], make_uint2(*(unsigned*)&p01, *(unsigned*)&p23));
}

// ---- h0 = emb[tok0] split to fp16 hi/lo ; reset barrier counters ----
__global__ void init_kernel(const int* __restrict__ tokens,
                            const float* __restrict__ emb)
{
    if (blockIdx.x == 0 && threadIdx.x < 8) g_bar[threadIdx.x * 32] = 0u;
    int b = blockIdx.x;
    long long tok = load_tok(tokens, b);
    int c = threadIdx.x * 4;
    float4 v = *(const float4*)(emb + tok * HID + c);
    __half h[4], l[4];
    split_h(v.x, h[0], l[0]); split_h(v.y, h[1], l[1]);
    split_h(v.z, h[2], l[2]); split_h(v.w, h[3], l[3]);
    __half2 hh01 = __halves2half2(h[0], h[1]), hh23 = __halves2half2(h[2], h[3]);
    __half2 ll01 = __halves2half2(l[0], l[1]), ll23 = __halves2half2(l[2], l[3]);
    size_t o = (size_t)b * HID + c;
    *(uint2*)&g_Hh[0][o] = make_uint2(*(unsigned*)&hh01, *(unsigned*)&hh23);
    *(uint2*)&g_Hl[0][o] = make_uint2(*(unsigned*)&ll01, *(unsigned*)&ll23);
}

// ================= PRELUDE: P[s] = E_s @ Wr + b, all steps in parallel ======
// 1024 blocks: (sg 0..7) x (rg 0..7) x (ct 0..15); each block does 32
// consecutive steps for its (rg, ct) tile with Wr resident in smem.
// Warp split: quadrant q = w&3, K half kh = w>>2; 2-term fp16 (Eh*Wh + Eh*Wl).

__device__ __forceinline__ void issue_Ep(PSMem& sm, int buf)
{
    const int t   = threadIdx.x;
    const int row = t >> 3;
    const int seg = (t & 7) * 64;
    const __half* src = g_E + (size_t)sm.stok[row] * HID + seg;
    __half* dst = &sm.E[buf][row][seg];
    #pragma unroll
    for (int i = 0; i < 8; ++i) cp_async16(dst + i * 8, src + i * 8);
    cp_commit();
}

__global__ void __launch_bounds__(256, 1)
prelude_kernel(const int* __restrict__ tokens,
               const float* __restrict__ Wr,
               const float* __restrict__ bias,
               int nsteps)
{
    extern __shared__ char raw[];
    PSMem& sm = *reinterpret_cast<PSMem*>(raw);

    const int tid = threadIdx.x;
    const int w   = tid >> 5;
    const int sg  = blockIdx.x >> 7;
    const int rg  = (blockIdx.x >> 4) & 7;
    const int ct  = blockIdx.x & 15;
    const int rb  = rg * 32, cb = ct * 32;

    // Wr slice, k-major, fp16 hi/lo
    {
        const int col = tid & 31;
        const int kr  = tid >> 5;
        for (int it = 0; it < 64; ++it) {
            int k = it * 8 + kr;
            float v = Wr[(size_t)k * HID + cb + col];
            __half h, l;
            split_h(v, h, l);
            sm.Wth[col][k] = h;
            sm.Wtl[col][k] = l;
        }
    }

    const int q  = w & 3, kh = w >> 2;
    const int mi = q >> 1, ni = q & 1;
    const int er = tid >> 3, ec0 = (tid & 7) * 4;
    const float4 bias4 = *(const float4*)(bias + cb + ec0);

    // token row for substep t (clamped for the one out-of-range slot)
    auto tokrow = [&](int t) -> int {
        int s = sg * 32 + t + 1;
        long long row = 2LL * s - 1;
        if (row > 2LL * (long long)(HID - 1) - 1) {}  // no-op; real clamp below
        if (row > 510) row = 510;
        return load_tok(tokens, row * BATCH + rb + (tid & 31));
    };

    if (tid < 32) sm.stok[tid] = tokrow(0);
    __syncthreads();
    issue_Ep(sm, 0);
    int tnext = 0;
    if (tid < 32) tnext = tokrow(1);

    for (int t = 0; t < 32; ++t) {
        const int s = sg * 32 + t + 1;
        cp_wait<0>();
        __syncthreads();                     // E(t) staged, visible

        if (t + 1 < 32) {                    // publish stok(t+1), issue E(t+1)
            if (tid < 32) sm.stok[tid] = tnext;
            __syncthreads();
            issue_Ep(sm, (t + 1) & 1);
        }

        wmma::fragment<wmma::accumulator, 16, 16, 16, float> acc;
        wmma::fill_fragment(acc, 0.0f);
        const int b = t & 1;
        #pragma unroll
        for (int kk = 0; kk < 16; ++kk) {
            const int k = kh * 256 + kk * 16;
            wmma::fragment<wmma::matrix_a, 16, 16, 16, __half, wmma::row_major> ah;
            wmma::fragment<wmma::matrix_b, 16, 16, 16, __half, wmma::col_major> bh, bl;
            wmma::load_matrix_sync(ah, &sm.E[b][mi * 16][k], AS);
            wmma::load_matrix_sync(bh, &sm.Wth[ni * 16][k], AS);
            wmma::load_matrix_sync(bl, &sm.Wtl[ni * 16][k], AS);
            wmma::mma_sync(acc, ah, bh, acc);
            wmma::mma_sync(acc, ah, bl, acc);
        }

        if (tid < 32 && t + 2 < 32) tnext = tokrow(t + 2);

        wmma::store_matrix_sync(&sm.red[w][0][0], acc, 20, wmma::mem_row_major);
        __syncthreads();

        if (s <= nsteps) {
            const int q2 = (er >> 4) * 2 + (ec0 >> 4);
            const int rr = er & 15, cc = ec0 & 15;
            float4 a = *(const float4*)&sm.red[q2][rr][cc];
            float4 c = *(const float4*)&sm.red[4 + q2][rr][cc];
            float4 o = make_float4(a.x + c.x + bias4.x, a.y + c.y + bias4.y,
                                   a.z + c.z + bias4.z, a.w + c.w + bias4.w);
            *(float4*)&g_P[((size_t)(s - 1) * BATCH + rb + er) * HID + cb + ec0] = o;
        }
        // next-iter red writes are ordered by the top-of-loop syncthreads
    }
}

// ================= CHAIN: H_s = tanh(H_{s-1} @ Wl + P_s), 255 steps =========

__device__ __forceinline__ void issue_Hc(CSMem& sm, int c, int s, int rb)
{
    const int t   = threadIdx.x;
    const int row = t >> 3;
    const int kb  = c * 256 + (t & 7) * 32;
    size_t o = (size_t)(rb + row) * HID + kb;
    const __half* sh = g_Hh[(s - 1) & 1] + o;
    const __half* sl = g_Hl[(s - 1) & 1] + o;
    #pragma unroll
    for (int i = 0; i < 4; ++i) {
        cp_async16(&sm.Hp[0][row][kb + i * 8], sh + i * 8);
        cp_async16(&sm.Hp[1][row][kb + i * 8], sl + i * 8);
    }
    cp_commit();
}

__device__ __forceinline__ void issue_P(CSMem& sm, int s, int rb, int cb)
{
    const int t   = threadIdx.x;
    const int row = t >> 3;
    const int c   = (t & 7) * 4;
    const float* src = g_P + ((size_t)(s - 1) * BATCH + rb + row) * HID + cb + c;
    cp_async16(&sm.Pb[s & 1][row][c], src);
    cp_commit();
}

__global__ void __launch_bounds__(256, 1)
chain_kernel(const float* __restrict__ Wl,
             float* __restrict__ out,
             int nsteps)
{
    extern __shared__ char raw[];
    CSMem& sm = *reinterpret_cast<CSMem*>(raw);

    const int tid = threadIdx.x;
    const int w   = tid >> 5;
    const int rg  = blockIdx.x >> 4;
    const int rb  = rg * 32;
    const int cb  = (blockIdx.x & 15) * 32;
    unsigned* barp = &g_bar[rg * 32];

    // Wl slice, k-major, fp16 hi/lo (resident all steps)
    {
        const int col = tid & 31;
        const int kr  = tid >> 5;
        for (int it = 0; it < 64; ++it) {
            int k = it * 8 + kr;
            float v = Wl[(size_t)k * HID + cb + col];
            __half h, l;
            split_h(v, h, l);
            sm.Wth[col][k] = h;
            sm.Wtl[col][k] = l;
        }
    }
    __syncthreads();

    const int er = tid >> 3, ec0 = (tid & 7) * 4;

    issue_P(sm, 1, rb, cb);                  // group: P(1)

    for (int s = 1; s <= nsteps; ++s) {
        // barrier: peers' step s-1 H writes must be visible
        if (s > 1) {
            if (tid == 0) {
                const unsigned target = 16u * (unsigned)(s - 1);
                while (bar_peek(barp) < target) { }
            }
        }
        __syncthreads();

        issue_Hc(sm, 0, s, rb);              // group: Hc0
        issue_Hc(sm, 1, s, rb);              // group: Hc1
        if (s < nsteps) issue_P(sm, s + 1, rb, cb);  // group: P(s+1)
        else            cp_commit();                  // empty group (uniform count)

        wmma::fragment<wmma::accumulator, 16, 16, 16, float> acc[2][2];
        #pragma unroll
        for (int mi = 0; mi < 2; ++mi)
            #pragma unroll
            for (int ni = 0; ni < 2; ++ni)
                wmma::fill_fragment(acc[mi][ni], 0.0f);

        // pending: P(s), Hc0, Hc1, P(s+1)
        #pragma unroll
        for (int c = 0; c < 2; ++c) {
            if (c == 0) cp_wait<2>(); else cp_wait<1>();
            __syncthreads();
            #pragma unroll
            for (int kk = 0; kk < 2; ++kk) {
                const int k = c * 256 + w * 32 + kk * 16;
                wmma::fragment<wmma::matrix_a, 16, 16, 16, __half, wmma::row_major> ah[2], al[2];
                wmma::fragment<wmma::matrix_b, 16, 16, 16, __half, wmma::col_major> bh[2], bl[2];
                #pragma unroll
                for (int mi = 0; mi < 2; ++mi) {
                    wmma::load_matrix_sync(ah[mi], &sm.Hp[0][mi * 16][k], AS);
                    wmma::load_matrix_sync(al[mi], &sm.Hp[1][mi * 16][k], AS);
                }
                #pragma unroll
                for (int ni = 0; ni < 2; ++ni) {
                    wmma::load_matrix_sync(bh[ni], &sm.Wth[ni * 16][k], AS);
                    wmma::load_matrix_sync(bl[ni], &sm.Wtl[ni * 16][k], AS);
                }
                #pragma unroll
                for (int mi = 0; mi < 2; ++mi)
                    #pragma unroll
                    for (int ni = 0; ni < 2; ++ni) {
                        wmma::mma_sync(acc[mi][ni], ah[mi], bh[ni], acc[mi][ni]);
                        wmma::mma_sync(acc[mi][ni], ah[mi], bl[ni], acc[mi][ni]);
                        wmma::mma_sync(acc[mi][ni], al[mi], bh[ni], acc[mi][ni]);
                    }
            }
        }

        // reduce 8 warp partials
        #pragma unroll
        for (int mi = 0; mi < 2; ++mi)
            #pragma unroll
            for (int ni = 0; ni < 2; ++ni)
                wmma::store_matrix_sync(&sm.red[w][mi * 16][ni * 16],
                                        acc[mi][ni], RPAD, wmma::mem_row_major);
        __syncthreads();

        // epilogue: sum partials + P tile, tanh, store fp16 hi/lo (or fp32 out)
        {
            float4 sum = *(const float4*)&sm.red[0][er][ec0];
            #pragma unroll
            for (int p = 1; p < 8; ++p) {
                float4 t = *(const float4*)&sm.red[p][er][ec0];
                sum.x += t.x; sum.y += t.y; sum.z += t.z; sum.w += t.w;
            }
            float4 pv = *(const float4*)&sm.Pb[s & 1][er][ec0];
            float v0 = tanhf(sum.x + pv.x);
            float v1 = tanhf(sum.y + pv.y);
            float v2 = tanhf(sum.z + pv.z);
            float v3 = tanhf(sum.w + pv.w);

            size_t o = (size_t)(rb + er) * HID + cb + ec0;
            if (s == nsteps) {
                *(float4*)&out[o] = make_float4(v0, v1, v2, v3);
            } else {
                __half h0, l0, h1, l1, h2, l2, h3, l3;
                split_h(v0, h0, l0); split_h(v1, h1, l1);
                split_h(v2, h2, l2); split_h(v3, h3, l3);
                __half2 hh01 = __halves2half2(h0, h1), hh23 = __halves2half2(h2, h3);
                __half2 ll01 = __halves2half2(l0, l1), ll23 = __halves2half2(l2, l3);
                *(uint2*)&g_Hh[s & 1][o] =
                    make_uint2(*(unsigned*)&hh01, *(unsigned*)&hh23);
                *(uint2*)&g_Hl[s & 1][o] =
                    make_uint2(*(unsigned*)&ll01, *(unsigned*)&ll23);
            }
        }

        if (s < nsteps) {
            __syncthreads();                 // all epilogue stores issued
            if (tid == 0) bar_arrive(barp);  // release: our H writes visible
        }
    }
}

extern "C" void kernel_launch(void* const* d_in, const int* in_sizes, int n_in,
                              void* d_out, int out_size)
{
    const int*   tokens = (const int*)  d_in[0];   // [511, 256]
    const float* emb    = (const float*)d_in[1];   // [32000, 512]
    const float* Wl     = (const float*)d_in[2];   // [512, 512]
    const float* Wr     = (const float*)d_in[3];   // [512, 512]
    const float* bias   = (const float*)d_in[4];   // [512]
    float* out = (float*)d_out;                    // [256, 512]

    const int T      = in_sizes[0] / BATCH;  // 511
    const int nsteps = (T - 1) / 2;          // 255 reduce steps
    const int nemb   = in_sizes[1];          // 32000*512

    cudaFuncSetAttribute(prelude_kernel,
                         cudaFuncAttributeMaxDynamicSharedMemorySize,
                         (int)sizeof(PSMem));
    cudaFuncSetAttribute(chain_kernel,
                         cudaFuncAttributeMaxDynamicSharedMemorySize,
                         (int)sizeof(CSMem));

    prep_emb<<<(nemb / 4 + 255) / 256, 256>>>(emb, nemb);
    init_kernel<<<BATCH, HID / 4>>>(tokens, emb);
    prelude_kernel<<<1024, 256, sizeof(PSMem)>>>(tokens, Wr, bias, nsteps);
    chain_kernel<<<NBLK, 256, sizeof(CSMem)>>>(Wl, out, nsteps);
}

// round 13
// speedup vs baseline: 1.0848x; 1.0848x over previous
#include <cuda_runtime.h>
#include <cuda_fp16.h>
#include <mma.h>
#include <cstddef>

using namespace nvcuda;

#define BATCH 256
#define HID   512
#define NBLK  128           // 8 row-groups x 16 col-tiles, all co-resident
#define WKS   1032          // W k-major stride (elems): 2064B rows, LDSM conflict-free
#define AS    520           // A row stride (elems): 1040B rows, LDSM conflict-free
#define RPAD  36            // reduction row stride (fp32), float4-aligned

// ---- scratch (static __device__, allocation-free per harness rules) ----
__device__ __half    g_E[32000 * HID];      // embedding, fp16 (unsplit)
__device__ __half    g_Hh[2][BATCH * HID];  // ping-pong hidden state, fp16 hi
__device__ __half    g_Hl[2][BATCH * HID];  // fp16 residual
__device__ unsigned  g_bar[8 * 32];         // per-row-group barrier counters

struct SMem {
    __half Wth[32][WKS];                 // 66048B  W col-slice, k-major, hi
    __half Wtl[32][WKS];                 // 66048B  lo
    __half E[32][AS];                    // 33280B  persistent E buffer
    union {
        __half Hp[2][32][AS];            // 66560B  H hi/lo staging
        float  red[8][32][RPAD];         // 36864B  warp-partial reduction
    } u;
    int stok[32];
};                                        // 232064B total (<= 232448 limit)

// tokens may be int32 (jax default) or int64. tokens[0][1] is a real token
// >= 3, so a zero second 32-bit word means little-endian int64.
__device__ __forceinline__ int load_tok(const int* tokens, long long idx)
{
    if (tokens[1] == 0) return (int)((const long long*)tokens)[idx];
    return tokens[idx];
}

__device__ __forceinline__ void split_h(float x, __half& hi, __half& lo)
{
    hi = __float2half_rn(x);
    lo = __float2half_rn(x - __half2float(hi));
}

__device__ __forceinline__ void cp_async16(void* dst, const void* src)
{
    unsigned d = (unsigned)__cvta_generic_to_shared(dst);
    asm volatile("cp.async.cg.shared.global [%0], [%1], 16;" :: "r"(d), "l"(src));
}
__device__ __forceinline__ void cp_commit()
{
    asm volatile("cp.async.commit_group;" ::: "memory");
}
template <int N> __device__ __forceinline__ void cp_wait()
{
    asm volatile("cp.async.wait_group %0;" :: "n"(N) : "memory");
}

__device__ __forceinline__ void bar_arrive(unsigned* p)
{
    asm volatile("red.release.gpu.global.add.u32 [%0], %1;"
                 :: "l"(p), "r"(1u) : "memory");
}
__device__ __forceinline__ unsigned bar_peek(const unsigned* p)
{
    unsigned v;
    asm volatile("ld.acquire.gpu.global.u32 %0, [%1];"
                 : "=r"(v) : "l"(p) : "memory");
    return v;
}

// ---- convert the embedding table to fp16 (single plane) ----
__global__ void prep_emb(const float* __restrict__ emb, int n)
{
    int e = (blockIdx.x * blockDim.x + threadIdx.x) * 4;
    if (e >= n) return;
    float4 v = __ldcs((const float4*)(emb + e));
    __half2 p01 = __floats2half2_rn(v.x, v.y);
    __half2 p23 = __floats2half2_rn(v.z, v.w);
    __stcs((uint2*)&g_E[e], make_uint2(*(unsigned*)&p01, *(unsigned*)&p23));
}

// ---- h0 = emb[tok0] split to fp16 hi/lo ; reset barrier counters ----
__global__ void init_kernel(const int* __restrict__ tokens,
                            const float* __restrict__ emb)
{
    if (blockIdx.x == 0 && threadIdx.x < 8) g_bar[threadIdx.x * 32] = 0u;
    int b = blockIdx.x;
    long long tok = load_tok(tokens, b);
    int c = threadIdx.x * 4;                    // 128 threads x 4 cols
    float4 v = *(const float4*)(emb + tok * HID + c);
    __half h[4], l[4];
    split_h(v.x, h[0], l[0]); split_h(v.y, h[1], l[1]);
    split_h(v.z, h[2], l[2]); split_h(v.w, h[3], l[3]);
    __half2 hh01 = __halves2half2(h[0], h[1]), hh23 = __halves2half2(h[2], h[3]);
    __half2 ll01 = __halves2half2(l[0], l[1]), ll23 = __halves2half2(l[2], l[3]);
    size_t o = (size_t)b * HID + c;
    *(uint2*)&g_Hh[0][o] = make_uint2(*(unsigned*)&hh01, *(unsigned*)&hh23);
    *(uint2*)&g_Hl[0][o] = make_uint2(*(unsigned*)&ll01, *(unsigned*)&ll23);
}

// issue cp.async: whole E tile (32 rows x 512) into the persistent E buffer
__device__ __forceinline__ void issue_E(SMem& sm)
{
    const int t   = threadIdx.x;
    const int row = t >> 3;
    const int seg = (t & 7) * 64;
    const __half* src = g_E + (size_t)sm.stok[row] * HID + seg;
    __half* dst = &sm.E[row][seg];
    #pragma unroll
    for (int i = 0; i < 8; ++i) cp_async16(dst + i * 8, src + i * 8);
    cp_commit();
}

// issue cp.async: both H chunks (K=512), hi+lo planes, ONE commit group
__device__ __forceinline__ void issue_H(SMem& sm, int s, int rb)
{
    const int t   = threadIdx.x;
    const int row = t >> 3;
    const int kb  = (t & 7) * 64;
    size_t o = (size_t)(rb + row) * HID + kb;
    const __half* sh = g_Hh[(s - 1) & 1] + o;
    const __half* sl = g_Hl[(s - 1) & 1] + o;
    #pragma unroll
    for (int i = 0; i < 8; ++i) {
        cp_async16(&sm.u.Hp[0][row][kb + i * 8], sh + i * 8);
        cp_async16(&sm.u.Hp[1][row][kb + i * 8], sl + i * 8);
    }
    cp_commit();
}

// one E-phase wmma slice: 2 terms at k-offset kl (E-local), W row HID+kl
__device__ __forceinline__ void mma_E(SMem& sm, int kl,
    wmma::fragment<wmma::accumulator, 16, 16, 16, float> (&acc)[2][2])
{
    const int kf = HID + kl;
    wmma::fragment<wmma::matrix_a, 16, 16, 16, __half, wmma::row_major> ah[2];
    wmma::fragment<wmma::matrix_b, 16, 16, 16, __half, wmma::col_major> bh[2], bl[2];
    #pragma unroll
    for (int mi = 0; mi < 2; ++mi)
        wmma::load_matrix_sync(ah[mi], &sm.E[mi * 16][kl], AS);
    #pragma unroll
    for (int ni = 0; ni < 2; ++ni) {
        wmma::load_matrix_sync(bh[ni], &sm.Wth[ni * 16][kf], WKS);
        wmma::load_matrix_sync(bl[ni], &sm.Wtl[ni * 16][kf], WKS);
    }
    #pragma unroll
    for (int mi = 0; mi < 2; ++mi)
        #pragma unroll
        for (int ni = 0; ni < 2; ++ni) {
            wmma::mma_sync(acc[mi][ni], ah[mi], bh[ni], acc[mi][ni]);
            wmma::mma_sync(acc[mi][ni], ah[mi], bl[ni], acc[mi][ni]);
        }
}

// Persistent chain kernel: 255 reduce steps, one launch.
// Block = 32x32 output tile; 8 warps split K. Per step:
//   E phase: K=512, E unsplit fp16, W split -> 2 terms (Eh*Wh + Eh*Wl)
//   H phase: K=512, H split fp16 hi/lo   -> 3 terms (HhWh + HhWl + HlWh)
// W slice (k-major, fp16 hi/lo) resident in smem for the whole kernel.
// Next step's E tile prefetched through the inter-block barrier; H staged
// after the barrier but its L2 latency is covered by the E kk2-3 compute.
__global__ void __launch_bounds__(256, 1)
chain_kernel(const int* __restrict__ tokens,
             const float* __restrict__ Wl,
             const float* __restrict__ Wr,
             const float* __restrict__ bias,
             float* __restrict__ out,
             int nsteps)
{
    extern __shared__ char smem_raw[];
    SMem& sm = *reinterpret_cast<SMem*>(smem_raw);

    const int tid = threadIdx.x;
    const int w   = tid >> 5;
    const int rg  = blockIdx.x >> 4;        // row group 0..7 (independent chains)
    const int rb  = rg * 32;
    const int cb  = (blockIdx.x & 15) * 32;
    unsigned* barp = &g_bar[rg * 32];

    // ---- one-time: load + split W col slice into k-major smem planes ----
    {
        const int col = tid & 31;
        const int kr  = tid >> 5;            // 8 k-rows per iter
        for (int it = 0; it < 128; ++it) {
            int k = it * 8 + kr;             // 0..1023 over [Wl ; Wr]
            float v = (k < HID) ? Wl[(size_t)k * HID + cb + col]
                                : Wr[(size_t)(k - HID) * HID + cb + col];
            __half h, l;
            split_h(v, h, l);
            sm.Wth[col][k] = h;
            sm.Wtl[col][k] = l;
        }
    }

    // epilogue role + cached bias
    const int er  = tid >> 3;
    const int ec0 = (tid & 7) * 4;
    const float4 bias4 = *(const float4*)(bias + cb + ec0);

    // prologue: step-1 tokens, then prefetch step-1 E
    if (tid < 32) sm.stok[tid] = load_tok(tokens, (long long)BATCH + rb + tid);
    __syncthreads();
    issue_E(sm);

    for (int s = 1; s <= nsteps; ++s) {
        // prefetch next step's tokens (off critical path; tokens L1-resident)
        int treg = 0;
        if (tid < 32 && s < nsteps)
            treg = load_tok(tokens, (long long)(2 * s + 1) * BATCH + rb + tid);

        wmma::fragment<wmma::accumulator, 16, 16, 16, float> acc[2][2];
        #pragma unroll
        for (int mi = 0; mi < 2; ++mi)
            #pragma unroll
            for (int ni = 0; ni < 2; ++ni)
                wmma::fill_fragment(acc[mi][ni], 0.0f);

        // ---- E staged? (issued at previous step's tail / prologue) ----
        cp_wait<0>();
        __syncthreads();

        // publish next step's tokens now: E(s) cp.async already captured its
        // addresses, and >=2 syncs separate this write from the tail's issue_E
        if (tid < 32 && s < nsteps) sm.stok[tid] = treg;

        // ---- E phase, first half (kk 0..1) ----
        mma_E(sm, w * 64 + 0,  acc);
        mma_E(sm, w * 64 + 16, acc);

        // ---- barrier: peers' step s-1 H writes must be visible ----
        if (s > 1) {
            if (tid == 0) {
                const unsigned target = 16u * (unsigned)(s - 1);
                while (bar_peek(barp) < target) { }
            }
        }
        __syncthreads();

        issue_H(sm, s, rb);                  // both H chunks, one group

        // ---- E phase, second half (kk 2..3): covers H flight ----
        mma_E(sm, w * 64 + 32, acc);
        mma_E(sm, w * 64 + 48, acc);

        cp_wait<0>();
        __syncthreads();

        // ---- H phase: K=512, 3 terms, warp owns 64 k-cols ----
        #pragma unroll
        for (int kk = 0; kk < 4; ++kk) {
            const int k = w * 64 + kk * 16;  // fused k (Wl half)
            wmma::fragment<wmma::matrix_a, 16, 16, 16, __half, wmma::row_major> ah[2], al[2];
            wmma::fragment<wmma::matrix_b, 16, 16, 16, __half, wmma::col_major> bh[2], bl[2];
            #pragma unroll
            for (int mi = 0; mi < 2; ++mi) {
                wmma::load_matrix_sync(ah[mi], &sm.u.Hp[0][mi * 16][k], AS);
                wmma::load_matrix_sync(al[mi], &sm.u.Hp[1][mi * 16][k], AS);
            }
            #pragma unroll
            for (int ni = 0; ni < 2; ++ni) {
                wmma::load_matrix_sync(bh[ni], &sm.Wth[ni * 16][k], WKS);
                wmma::load_matrix_sync(bl[ni], &sm.Wtl[ni * 16][k], WKS);
            }
            #pragma unroll
            for (int mi = 0; mi < 2; ++mi)
                #pragma unroll
                for (int ni = 0; ni < 2; ++ni) {
                    wmma::mma_sync(acc[mi][ni], ah[mi], bh[ni], acc[mi][ni]);
                    wmma::mma_sync(acc[mi][ni], ah[mi], bl[ni], acc[mi][ni]);
                    wmma::mma_sync(acc[mi][ni], al[mi], bh[ni], acc[mi][ni]);
                }
        }
        __syncthreads();                     // H reads done; red overlays Hp

        // ---- reduce 8 warp partials ----
        #pragma unroll
        for (int mi = 0; mi < 2; ++mi)
            #pragma unroll
            for (int ni = 0; ni < 2; ++ni)
                wmma::store_matrix_sync(&sm.u.red[w][mi * 16][ni * 16],
                                        acc[mi][ni], RPAD, wmma::mem_row_major);
        __syncthreads();

        // ---- epilogue: bias + tanh; write fp16 hi/lo planes (or fp32 out) ----
        {
            float4 sum = *(const float4*)&sm.u.red[0][er][ec0];
            #pragma unroll
            for (int p = 1; p < 8; ++p) {
                float4 t = *(const float4*)&sm.u.red[p][er][ec0];
                sum.x += t.x; sum.y += t.y; sum.z += t.z; sum.w += t.w;
            }
            float v0 = tanhf(sum.x + bias4.x);
            float v1 = tanhf(sum.y + bias4.y);
            float v2 = tanhf(sum.z + bias4.z);
            float v3 = tanhf(sum.w + bias4.w);

            size_t o = (size_t)(rb + er) * HID + cb + ec0;
            if (s == nsteps) {
                *(float4*)&out[o] = make_float4(v0, v1, v2, v3);
            } else {
                __half h0, l0, h1, l1, h2, l2, h3, l3;
                split_h(v0, h0, l0); split_h(v1, h1, l1);
                split_h(v2, h2, l2); split_h(v3, h3, l3);
                __half2 hh01 = __halves2half2(h0, h1), hh23 = __halves2half2(h2, h3);
                __half2 ll01 = __halves2half2(l0, l1), ll23 = __halves2half2(l2, l3);
                *(uint2*)&g_Hh[s & 1][o] =
                    make_uint2(*(unsigned*)&hh01, *(unsigned*)&hh23);
                *(uint2*)&g_Hl[s & 1][o] =
                    make_uint2(*(unsigned*)&ll01, *(unsigned*)&ll23);
            }
        }

        if (s < nsteps) {
            __syncthreads();                 // all epilogue stores issued
            if (tid == 0) bar_arrive(barp);  // release: our H writes visible
            issue_E(sm);                     // next E flies through the barrier
        }
    }
}

extern "C" void kernel_launch(void* const* d_in, const int* in_sizes, int n_in,
                              void* d_out, int out_size)
{
    const int*   tokens = (const int*)  d_in[0];   // [511, 256]
    const float* emb    = (const float*)d_in[1];   // [32000, 512]
    const float* Wl     = (const float*)d_in[2];   // [512, 512]
    const float* Wr     = (const float*)d_in[3];   // [512, 512]
    const float* bias   = (const float*)d_in[4];   // [512]
    float* out = (float*)d_out;                    // [256, 512]

    const int T      = in_sizes[0] / BATCH;  // 511
    const int nsteps = (T - 1) / 2;          // 255 reduce steps
    const int nemb   = in_sizes[1];          // 32000*512

    cudaFuncSetAttribute(chain_kernel,
                         cudaFuncAttributeMaxDynamicSharedMemorySize,
                         (int)sizeof(SMem));

    prep_emb<<<(nemb / 4 + 255) / 256, 256>>>(emb, nemb);
    init_kernel<<<BATCH, HID / 4>>>(tokens, emb);
    chain_kernel<<<NBLK, 256, sizeof(SMem)>>>(tokens, Wl, Wr, bias, out, nsteps);
}

// round 14
// speedup vs baseline: 1.1160x; 1.0288x over previous
#include <cuda_runtime.h>
#include <cuda_fp16.h>
#include <mma.h>
#include <cstddef>

using namespace nvcuda;

#define BATCH 256
#define HID   512
#define NBLK  128           // 8 row-groups x 16 col-tiles, all co-resident
#define WKS   1032          // W k-major stride (elems): 2064B rows, LDSM conflict-free
#define AS    520           // A row stride (elems): 1040B rows, LDSM conflict-free
#define RPAD  36            // reduction row stride (fp32), float4-aligned

// ---- scratch (static __device__, allocation-free per harness rules) ----
__device__ __half    g_E[32000 * HID];      // embedding, fp16 (unsplit)
__device__ __half    g_Hh[2][BATCH * HID];  // ping-pong hidden state, fp16 hi
__device__ __half    g_Hl[2][BATCH * HID];  // fp16 residual
__device__ unsigned  g_bar[8 * 32];         // per-row-group barrier counters

struct SMem {
    __half Wth[32][WKS];                 // 66048B  W col-slice, k-major, hi
    __half Wtl[32][WKS];                 // 66048B  lo
    __half E[32][AS];                    // 33280B  persistent E buffer
    union {
        __half Hp[2][32][AS];            // 66560B  H hi/lo staging
        float  red[8][32][RPAD];         // 36864B  warp-partial reduction
    } u;
    int stok[32];
};                                        // 232064B total (<= 232448 limit)

// tokens may be int32 (jax default) or int64. tokens[0][1] is a real token
// >= 3, so a zero second 32-bit word means little-endian int64.
__device__ __forceinline__ int load_tok(const int* tokens, long long idx)
{
    if (tokens[1] == 0) return (int)((const long long*)tokens)[idx];
    return tokens[idx];
}

__device__ __forceinline__ void split_h(float x, __half& hi, __half& lo)
{
    hi = __float2half_rn(x);
    lo = __float2half_rn(x - __half2float(hi));
}

// tanh(x) = 1 - 2/(exp2(2x*log2e) + 1); ex2/rcp approx err ~2^-22 -> ~1e-6.
// Saturates correctly: x->+inf: rcp(inf)=0 -> 1; x->-inf: e->0 -> -1.
__device__ __forceinline__ float fast_tanh(float x)
{
    float e;
    asm("ex2.approx.f32 %0, %1;" : "=f"(e) : "f"(x * 2.885390081777927f));
    float r;
    asm("rcp.approx.f32 %0, %1;" : "=f"(r) : "f"(e + 1.0f));
    return fmaf(-2.0f, r, 1.0f);
}

__device__ __forceinline__ void cp_async16(void* dst, const void* src)
{
    unsigned d = (unsigned)__cvta_generic_to_shared(dst);
    asm volatile("cp.async.cg.shared.global [%0], [%1], 16;" :: "r"(d), "l"(src));
}
__device__ __forceinline__ void cp_commit()
{
    asm volatile("cp.async.commit_group;" ::: "memory");
}
template <int N> __device__ __forceinline__ void cp_wait()
{
    asm volatile("cp.async.wait_group %0;" :: "n"(N) : "memory");
}

__device__ __forceinline__ void bar_arrive(unsigned* p)
{
    asm volatile("red.release.gpu.global.add.u32 [%0], %1;"
                 :: "l"(p), "r"(1u) : "memory");
}
__device__ __forceinline__ unsigned bar_peek(const unsigned* p)
{
    unsigned v;
    asm volatile("ld.acquire.gpu.global.u32 %0, [%1];"
                 : "=r"(v) : "l"(p) : "memory");
    return v;
}

// ---- convert the embedding table to fp16 (single plane) ----
__global__ void prep_emb(const float* __restrict__ emb, int n)
{
    int e = (blockIdx.x * blockDim.x + threadIdx.x) * 4;
    if (e >= n) return;
    float4 v = __ldcs((const float4*)(emb + e));
    __half2 p01 = __floats2half2_rn(v.x, v.y);
    __half2 p23 = __floats2half2_rn(v.z, v.w);
    __stcs((uint2*)&g_E[e], make_uint2(*(unsigned*)&p01, *(unsigned*)&p23));
}

// ---- h0 = emb[tok0] split to fp16 hi/lo ; reset barrier counters ----
__global__ void init_kernel(const int* __restrict__ tokens,
                            const float* __restrict__ emb)
{
    if (blockIdx.x == 0 && threadIdx.x < 8) g_bar[threadIdx.x * 32] = 0u;
    int b = blockIdx.x;
    long long tok = load_tok(tokens, b);
    int c = threadIdx.x * 4;                    // 128 threads x 4 cols
    float4 v = *(const float4*)(emb + tok * HID + c);
    __half h[4], l[4];
    split_h(v.x, h[0], l[0]); split_h(v.y, h[1], l[1]);
    split_h(v.z, h[2], l[2]); split_h(v.w, h[3], l[3]);
    __half2 hh01 = __halves2half2(h[0], h[1]), hh23 = __halves2half2(h[2], h[3]);
    __half2 ll01 = __halves2half2(l[0], l[1]), ll23 = __halves2half2(l[2], l[3]);
    size_t o = (size_t)b * HID + c;
    *(uint2*)&g_Hh[0][o] = make_uint2(*(unsigned*)&hh01, *(unsigned*)&hh23);
    *(uint2*)&g_Hl[0][o] = make_uint2(*(unsigned*)&ll01, *(unsigned*)&ll23);
}

// issue cp.async: whole E tile (32 rows x 512) into the persistent E buffer
__device__ __forceinline__ void issue_E(SMem& sm)
{
    const int t   = threadIdx.x;
    const int row = t >> 3;
    const int seg = (t & 7) * 64;
    const __half* src = g_E + (size_t)sm.stok[row] * HID + seg;
    __half* dst = &sm.E[row][seg];
    #pragma unroll
    for (int i = 0; i < 8; ++i) cp_async16(dst + i * 8, src + i * 8);
    cp_commit();
}

// issue cp.async: H chunk c (k in [c*256, c*256+256)), hi+lo planes
__device__ __forceinline__ void issue_Hc(SMem& sm, int c, int s, int rb)
{
    const int t   = threadIdx.x;
    const int row = t >> 3;
    const int kb  = c * 256 + (t & 7) * 32;
    size_t o = (size_t)(rb + row) * HID + kb;
    const __half* sh = g_Hh[(s - 1) & 1] + o;
    const __half* sl = g_Hl[(s - 1) & 1] + o;
    #pragma unroll
    for (int i = 0; i < 4; ++i) {
        cp_async16(&sm.u.Hp[0][row][kb + i * 8], sh + i * 8);
        cp_async16(&sm.u.Hp[1][row][kb + i * 8], sl + i * 8);
    }
    cp_commit();
}

// Persistent chain kernel: 255 reduce steps, one launch.
// Block = 32x32 output tile; 8 warps split K. Per step:
//   E phase: K=512, E unsplit fp16, W split -> 2 terms (Eh*Wh + Eh*Wl)
//   H phase: K=512, H split fp16 hi/lo   -> 3 terms (HhWh + HhWl + HlWh)
// W slice (k-major, fp16 hi/lo) resident in smem for the whole kernel.
// cp.async groups per step (issued after the barrier, FIFO retirement):
//   g0=Hc0, g1=Hc1, g2=E(s+1).  wait<2> -> Hc0, wait<1> -> Hc1; E(s+1)
//   stays in flight through H compute + reduction + epilogue + barrier spin,
//   so next top's wait<0> is a no-op.
__global__ void __launch_bounds__(256, 1)
chain_kernel(const int* __restrict__ tokens,
             const float* __restrict__ Wl,
             const float* __restrict__ Wr,
             const float* __restrict__ bias,
             float* __restrict__ out,
             int nsteps)
{
    extern __shared__ char smem_raw[];
    SMem& sm = *reinterpret_cast<SMem*>(smem_raw);

    const int tid = threadIdx.x;
    const int w   = tid >> 5;
    const int rg  = blockIdx.x >> 4;        // row group 0..7 (independent chains)
    const int rb  = rg * 32;
    const int cb  = (blockIdx.x & 15) * 32;
    unsigned* barp = &g_bar[rg * 32];

    // ---- one-time: load + split W col slice into k-major smem planes ----
    {
        const int col = tid & 31;
        const int kr  = tid >> 5;            // 8 k-rows per iter
        for (int it = 0; it < 128; ++it) {
            int k = it * 8 + kr;             // 0..1023 over [Wl ; Wr]
            float v = (k < HID) ? Wl[(size_t)k * HID + cb + col]
                                : Wr[(size_t)(k - HID) * HID + cb + col];
            __half h, l;
            split_h(v, h, l);
            sm.Wth[col][k] = h;
            sm.Wtl[col][k] = l;
        }
    }

    // epilogue role + cached bias
    const int er  = tid >> 3;
    const int ec0 = (tid & 7) * 4;
    const float4 bias4 = *(const float4*)(bias + cb + ec0);

    // prologue: step-1 tokens, then prefetch step-1 E
    if (tid < 32) sm.stok[tid] = load_tok(tokens, (long long)BATCH + rb + tid);
    __syncthreads();
    issue_E(sm);

    for (int s = 1; s <= nsteps; ++s) {
        // prefetch next step's tokens (off critical path; tokens L1-resident)
        int treg = 0;
        if (tid < 32 && s < nsteps)
            treg = load_tok(tokens, (long long)(2 * s + 1) * BATCH + rb + tid);

        wmma::fragment<wmma::accumulator, 16, 16, 16, float> acc[2][2];
        #pragma unroll
        for (int mi = 0; mi < 2; ++mi)
            #pragma unroll
            for (int ni = 0; ni < 2; ++ni)
                wmma::fill_fragment(acc[mi][ni], 0.0f);

        // ---- E(s) staged? (group issued post-barrier last step / prologue) ----
        cp_wait<0>();
        __syncthreads();

        // publish next step's tokens: E(s) cp.async already captured its
        // addresses; the barrier sync below orders this before issue_E reads
        if (tid < 32 && s < nsteps) sm.stok[tid] = treg;

        // ---- E phase: K=512, 2 terms, warp owns 64 k-cols ----
        #pragma unroll
        for (int kk = 0; kk < 4; ++kk) {
            const int kl = w * 64 + kk * 16;       // within E's K
            const int kf = HID + kl;               // fused k (Wr half)
            wmma::fragment<wmma::matrix_a, 16, 16, 16, __half, wmma::row_major> ah[2];
            wmma::fragment<wmma::matrix_b, 16, 16, 16, __half, wmma::col_major> bh[2], bl[2];
            #pragma unroll
            for (int mi = 0; mi < 2; ++mi)
                wmma::load_matrix_sync(ah[mi], &sm.E[mi * 16][kl], AS);
            #pragma unroll
            for (int ni = 0; ni < 2; ++ni) {
                wmma::load_matrix_sync(bh[ni], &sm.Wth[ni * 16][kf], WKS);
                wmma::load_matrix_sync(bl[ni], &sm.Wtl[ni * 16][kf], WKS);
            }
            #pragma unroll
            for (int mi = 0; mi < 2; ++mi)
                #pragma unroll
                for (int ni = 0; ni < 2; ++ni) {
                    wmma::mma_sync(acc[mi][ni], ah[mi], bh[ni], acc[mi][ni]);
                    wmma::mma_sync(acc[mi][ni], ah[mi], bl[ni], acc[mi][ni]);
                }
        }

        // ---- barrier: peers' step s-1 H writes must be visible ----
        if (s > 1) {
            if (tid == 0) {
                const unsigned target = 16u * (unsigned)(s - 1);
                while (bar_peek(barp) < target) { }
            }
        }
        __syncthreads();   // also orders: last E reads before issue_E overwrite

        issue_Hc(sm, 0, s, rb);              // g0
        issue_Hc(sm, 1, s, rb);              // g1
        if (s < nsteps) issue_E(sm);         // g2: flies until next top
        else            cp_commit();         // empty g2 (uniform group count)

        // ---- H phase: K=512, 3 terms, 2 chunks, warp owns 32 k-cols/chunk ----
        #pragma unroll
        for (int c = 0; c < 2; ++c) {
            if (c == 0) cp_wait<2>(); else cp_wait<1>();
            __syncthreads();
            #pragma unroll
            for (int kk = 0; kk < 2; ++kk) {
                const int k = c * 256 + w * 32 + kk * 16;  // fused k (Wl half)
                wmma::fragment<wmma::matrix_a, 16, 16, 16, __half, wmma::row_major> ah[2], al[2];
                wmma::fragment<wmma::matrix_b, 16, 16, 16, __half, wmma::col_major> bh[2], bl[2];
                #pragma unroll
                for (int mi = 0; mi < 2; ++mi) {
                    wmma::load_matrix_sync(ah[mi], &sm.u.Hp[0][mi * 16][k], AS);
                    wmma::load_matrix_sync(al[mi], &sm.u.Hp[1][mi * 16][k], AS);
                }
                #pragma unroll
                for (int ni = 0; ni < 2; ++ni) {
                    wmma::load_matrix_sync(bh[ni], &sm.Wth[ni * 16][k], WKS);
                    wmma::load_matrix_sync(bl[ni], &sm.Wtl[ni * 16][k], WKS);
                }
                #pragma unroll
                for (int mi = 0; mi < 2; ++mi)
                    #pragma unroll
                    for (int ni = 0; ni < 2; ++ni) {
                        wmma::mma_sync(acc[mi][ni], ah[mi], bh[ni], acc[mi][ni]);
                        wmma::mma_sync(acc[mi][ni], ah[mi], bl[ni], acc[mi][ni]);
                        wmma::mma_sync(acc[mi][ni], al[mi], bh[ni], acc[mi][ni]);
                    }
            }
        }
        __syncthreads();                     // H reads done; red overlays Hp

        // ---- reduce 8 warp partials ----
        #pragma unroll
        for (int mi = 0; mi < 2; ++mi)
            #pragma unroll
            for (int ni = 0; ni < 2; ++ni)
                wmma::store_matrix_sync(&sm.u.red[w][mi * 16][ni * 16],
                                        acc[mi][ni], RPAD, wmma::mem_row_major);
        __syncthreads();

        // ---- epilogue: bias + tanh; write fp16 hi/lo planes (or fp32 out) ----
        {
            float4 sum = *(const float4*)&sm.u.red[0][er][ec0];
            #pragma unroll
            for (int p = 1; p < 8; ++p) {
                float4 t = *(const float4*)&sm.u.red[p][er][ec0];
                sum.x += t.x; sum.y += t.y; sum.z += t.z; sum.w += t.w;
            }
            float v0 = fast_tanh(sum.x + bias4.x);
            float v1 = fast_tanh(sum.y + bias4.y);
            float v2 = fast_tanh(sum.z + bias4.z);
            float v3 = fast_tanh(sum.w + bias4.w);

            size_t o = (size_t)(rb + er) * HID + cb + ec0;
            if (s == nsteps) {
                *(float4*)&out[o] = make_float4(v0, v1, v2, v3);
            } else {
                __half h0, l0, h1, l1, h2, l2, h3, l3;
                split_h(v0, h0, l0); split_h(v1, h1, l1);
                split_h(v2, h2, l2); split_h(v3, h3, l3);
                __half2 hh01 = __halves2half2(h0, h1), hh23 = __halves2half2(h2, h3);
                __half2 ll01 = __halves2half2(l0, l1), ll23 = __halves2half2(l2, l3);
                *(uint2*)&g_Hh[s & 1][o] =
                    make_uint2(*(unsigned*)&hh01, *(unsigned*)&hh23);
                *(uint2*)&g_Hl[s & 1][o] =
                    make_uint2(*(unsigned*)&ll01, *(unsigned*)&ll23);
            }
        }

        if (s < nsteps) {
            __syncthreads();                 // all epilogue stores issued
            if (tid == 0) bar_arrive(barp);  // release: our H writes visible
        }
    }
}

extern "C" void kernel_launch(void* const* d_in, const int* in_sizes, int n_in,
                              void* d_out, int out_size)
{
    const int*   tokens = (const int*)  d_in[0];   // [511, 256]
    const float* emb    = (const float*)d_in[1];   // [32000, 512]
    const float* Wl     = (const float*)d_in[2];   // [512, 512]
    const float* Wr     = (const float*)d_in[3];   // [512, 512]
    const float* bias   = (const float*)d_in[4];   // [512]
    float* out = (float*)d_out;                    // [256, 512]

    const int T      = in_sizes[0] / BATCH;  // 511
    const int nsteps = (T - 1) / 2;          // 255 reduce steps
    const int nemb   = in_sizes[1];          // 32000*512

    cudaFuncSetAttribute(chain_kernel,
                         cudaFuncAttributeMaxDynamicSharedMemorySize,
                         (int)sizeof(SMem));

    prep_emb<<<(nemb / 4 + 255) / 256, 256>>>(emb, nemb);
    init_kernel<<<BATCH, HID / 4>>>(tokens, emb);
    chain_kernel<<<NBLK, 256, sizeof(SMem)>>>(tokens, Wl, Wr, bias, out, nsteps);
}

// round 15
// speedup vs baseline: 1.2069x; 1.0814x over previous
#include <cuda_runtime.h>
#include <cuda_fp16.h>
#include <mma.h>
#include <cstddef>

using namespace nvcuda;

#define BATCH 256
#define HID   512
#define NBLK  128           // 8 row-groups x 16 col-tiles, all co-resident
#define WKS   1032          // W k-major stride (elems): 2064B rows, LDSM conflict-free
#define AS    520           // A row stride (elems): 1040B rows, LDSM conflict-free
#define RPAD  36            // reduction row stride (fp32), float4-aligned

// ---- scratch (static __device__, allocation-free per harness rules) ----
__device__ __half    g_E[32000 * HID];      // embedding, fp16 (unsplit)
__device__ __half    g_Hh[2][BATCH * HID];  // ping-pong hidden state, fp16 hi
__device__ __half    g_Hl[2][BATCH * HID];  // fp16 residual
__device__ unsigned  g_bar[8 * 32];         // per-row-group barrier counters

struct SMem {
    __half Wth[32][WKS];                 // 66048B  W col-slice, k-major, hi
    __half Wtl[32][WKS];                 // 66048B  lo
    __half E[32][AS];                    // 33280B  persistent E buffer
    union {
        __half Hp[2][32][AS];            // 66560B  H hi/lo staging
        float  red[8][32][RPAD];         // 36864B  warp-partial reduction
    } u;
    int stok[32];
};                                        // 232064B total (<= 232448 limit)

// tokens may be int32 (jax default) or int64. tokens[0][1] is a real token
// >= 3, so a zero second 32-bit word means little-endian int64.
__device__ __forceinline__ int load_tok(const int* tokens, long long idx)
{
    if (tokens[1] == 0) return (int)((const long long*)tokens)[idx];
    return tokens[idx];
}

__device__ __forceinline__ void split_h(float x, __half& hi, __half& lo)
{
    hi = __float2half_rn(x);
    lo = __float2half_rn(x - __half2float(hi));
}

// tanh(x) = 1 - 2/(exp2(2x*log2e) + 1); ex2/rcp approx err ~1e-6.
// Saturates correctly: x->+inf: rcp(inf)=0 -> 1; x->-inf: e->0 -> -1.
__device__ __forceinline__ float fast_tanh(float x)
{
    float e;
    asm("ex2.approx.f32 %0, %1;" : "=f"(e) : "f"(x * 2.885390081777927f));
    float r;
    asm("rcp.approx.f32 %0, %1;" : "=f"(r) : "f"(e + 1.0f));
    return fmaf(-2.0f, r, 1.0f);
}

__device__ __forceinline__ void cp_async16(void* dst, const void* src)
{
    unsigned d = (unsigned)__cvta_generic_to_shared(dst);
    asm volatile("cp.async.cg.shared.global [%0], [%1], 16;" :: "r"(d), "l"(src));
}
__device__ __forceinline__ void cp_commit()
{
    asm volatile("cp.async.commit_group;" ::: "memory");
}
template <int N> __device__ __forceinline__ void cp_wait()
{
    asm volatile("cp.async.wait_group %0;" :: "n"(N) : "memory");
}

__device__ __forceinline__ void bar_arrive(unsigned* p)
{
    asm volatile("red.release.gpu.global.add.u32 [%0], %1;"
                 :: "l"(p), "r"(1u) : "memory");
}
__device__ __forceinline__ unsigned bar_peek(const unsigned* p)
{
    unsigned v;
    asm volatile("ld.acquire.gpu.global.u32 %0, [%1];"
                 : "=r"(v) : "l"(p) : "memory");
    return v;
}

// ---- convert the embedding table to fp16 (single plane) ----
__global__ void prep_emb(const float* __restrict__ emb, int n)
{
    int e = (blockIdx.x * blockDim.x + threadIdx.x) * 4;
    if (e >= n) return;
    float4 v = __ldcs((const float4*)(emb + e));
    __half2 p01 = __floats2half2_rn(v.x, v.y);
    __half2 p23 = __floats2half2_rn(v.z, v.w);
    __stcs((uint2*)&g_E[e], make_uint2(*(unsigned*)&p01, *(unsigned*)&p23));
}

// ---- h0 = emb[tok0] split to fp16 hi/lo ; reset barrier counters ----
__global__ void init_kernel(const int* __restrict__ tokens,
                            const float* __restrict__ emb)
{
    if (blockIdx.x == 0 && threadIdx.x < 8) g_bar[threadIdx.x * 32] = 0u;
    int b = blockIdx.x;
    long long tok = load_tok(tokens, b);
    int c = threadIdx.x * 4;                    // 128 threads x 4 cols
    float4 v = *(const float4*)(emb + tok * HID + c);
    __half h[4], l[4];
    split_h(v.x, h[0], l[0]); split_h(v.y, h[1], l[1]);
    split_h(v.z, h[2], l[2]); split_h(v.w, h[3], l[3]);
    __half2 hh01 = __halves2half2(h[0], h[1]), hh23 = __halves2half2(h[2], h[3]);
    __half2 ll01 = __halves2half2(l[0], l[1]), ll23 = __halves2half2(l[2], l[3]);
    size_t o = (size_t)b * HID + c;
    *(uint2*)&g_Hh[0][o] = make_uint2(*(unsigned*)&hh01, *(unsigned*)&hh23);
    *(uint2*)&g_Hl[0][o] = make_uint2(*(unsigned*)&ll01, *(unsigned*)&ll23);
}

// issue cp.async: whole E tile (32 rows x 512) into the persistent E buffer
__device__ __forceinline__ void issue_E(SMem& sm)
{
    const int t   = threadIdx.x;
    const int row = t >> 3;
    const int seg = (t & 7) * 64;
    const __half* src = g_E + (size_t)sm.stok[row] * HID + seg;
    __half* dst = &sm.E[row][seg];
    #pragma unroll
    for (int i = 0; i < 8; ++i) cp_async16(dst + i * 8, src + i * 8);
    cp_commit();
}

// issue cp.async: H chunk c (k in [c*256, c*256+256)), hi+lo planes
__device__ __forceinline__ void issue_Hc(SMem& sm, int c, int s, int rb)
{
    const int t   = threadIdx.x;
    const int row = t >> 3;
    const int kb  = c * 256 + (t & 7) * 32;
    size_t o = (size_t)(rb + row) * HID + kb;
    const __half* sh = g_Hh[(s - 1) & 1] + o;
    const __half* sl = g_Hl[(s - 1) & 1] + o;
    #pragma unroll
    for (int i = 0; i < 4; ++i) {
        cp_async16(&sm.u.Hp[0][row][kb + i * 8], sh + i * 8);
        cp_async16(&sm.u.Hp[1][row][kb + i * 8], sl + i * 8);
    }
    cp_commit();
}

// Persistent chain kernel: 255 reduce steps, one launch.
// Block = 32x32 output tile; 8 warps split K. Per step:
//   E phase: K=512, E unsplit fp16, W split -> 2 terms (Eh*Wh + Eh*Wl)
//   H phase: K=512, H split fp16 hi/lo   -> 3 terms (HhWh + HhWl + HlWh)
// W slice (k-major, fp16 hi/lo) resident in smem for the whole kernel.
// Speculative H staging: if the inter-block barrier is ALREADY satisfied at
// the top of the step (checked with per-thread acquire loads BEFORE issuing,
// made uniform by __syncthreads_and), the H cp.asyncs are issued immediately
// and their flight hides under the E-phase MMAs; otherwise fall back to the
// proven R11 path (E-mma -> spin -> sync -> issue).
__global__ void __launch_bounds__(256, 1)
chain_kernel(const int* __restrict__ tokens,
             const float* __restrict__ Wl,
             const float* __restrict__ Wr,
             const float* __restrict__ bias,
             float* __restrict__ out,
             int nsteps)
{
    extern __shared__ char smem_raw[];
    SMem& sm = *reinterpret_cast<SMem*>(smem_raw);

    const int tid = threadIdx.x;
    const int w   = tid >> 5;
    const int rg  = blockIdx.x >> 4;        // row group 0..7 (independent chains)
    const int rb  = rg * 32;
    const int cb  = (blockIdx.x & 15) * 32;
    unsigned* barp = &g_bar[rg * 32];

    // ---- one-time: load + split W col slice into k-major smem planes ----
    {
        const int col = tid & 31;
        const int kr  = tid >> 5;            // 8 k-rows per iter
        for (int it = 0; it < 128; ++it) {
            int k = it * 8 + kr;             // 0..1023 over [Wl ; Wr]
            float v = (k < HID) ? Wl[(size_t)k * HID + cb + col]
                                : Wr[(size_t)(k - HID) * HID + cb + col];
            __half h, l;
            split_h(v, h, l);
            sm.Wth[col][k] = h;
            sm.Wtl[col][k] = l;
        }
    }

    // epilogue role + cached bias
    const int er  = tid >> 3;
    const int ec0 = (tid & 7) * 4;
    const float4 bias4 = *(const float4*)(bias + cb + ec0);

    // prologue: step-1 tokens, then prefetch step-1 E
    if (tid < 32) sm.stok[tid] = load_tok(tokens, (long long)BATCH + rb + tid);
    __syncthreads();
    issue_E(sm);

    for (int s = 1; s <= nsteps; ++s) {
        // prefetch next step's tokens (off critical path; tokens L1-resident)
        int treg = 0;
        if (tid < 32 && s < nsteps)
            treg = load_tok(tokens, (long long)(2 * s + 1) * BATCH + rb + tid);

        wmma::fragment<wmma::accumulator, 16, 16, 16, float> acc[2][2];
        #pragma unroll
        for (int mi = 0; mi < 2; ++mi)
            #pragma unroll
            for (int ni = 0; ni < 2; ++ni)
                wmma::fill_fragment(acc[mi][ni], 0.0f);

        // ---- E staged? (issued at previous step's tail / prologue) ----
        cp_wait<0>();
        __syncthreads();

        // publish next step's tokens: E(s) cp.async already captured its
        // addresses; multiple syncs separate this from the tail's issue_E
        if (tid < 32 && s < nsteps) sm.stok[tid] = treg;

        // ---- speculative barrier check (uniform; acquire BEFORE issue) ----
        const unsigned target = 16u * (unsigned)(s - 1);
        int pred = (s == 1) || (bar_peek(barp) >= target);
        int fast = __syncthreads_and(pred);
        if (fast) {                          // peers' H already visible:
            issue_Hc(sm, 0, s, rb);          //   stage now; flight hides
            issue_Hc(sm, 1, s, rb);          //   under the E-phase MMAs
        }

        // ---- E phase: K=512, 2 terms, warp owns 64 k-cols ----
        #pragma unroll
        for (int kk = 0; kk < 4; ++kk) {
            const int kl = w * 64 + kk * 16;       // within E's K
            const int kf = HID + kl;               // fused k (Wr half)
            wmma::fragment<wmma::matrix_a, 16, 16, 16, __half, wmma::row_major> ah[2];
            wmma::fragment<wmma::matrix_b, 16, 16, 16, __half, wmma::col_major> bh[2], bl[2];
            #pragma unroll
            for (int mi = 0; mi < 2; ++mi)
                wmma::load_matrix_sync(ah[mi], &sm.E[mi * 16][kl], AS);
            #pragma unroll
            for (int ni = 0; ni < 2; ++ni) {
                wmma::load_matrix_sync(bh[ni], &sm.Wth[ni * 16][kf], WKS);
                wmma::load_matrix_sync(bl[ni], &sm.Wtl[ni * 16][kf], WKS);
            }
            #pragma unroll
            for (int mi = 0; mi < 2; ++mi)
                #pragma unroll
                for (int ni = 0; ni < 2; ++ni) {
                    wmma::mma_sync(acc[mi][ni], ah[mi], bh[ni], acc[mi][ni]);
                    wmma::mma_sync(acc[mi][ni], ah[mi], bl[ni], acc[mi][ni]);
                }
        }

        // ---- slow path: spin until peers' step s-1 H writes visible ----
        if (!fast) {
            if (tid == 0) {
                while (bar_peek(barp) < target) { }
            }
            __syncthreads();
            issue_Hc(sm, 0, s, rb);
            issue_Hc(sm, 1, s, rb);
        }

        // ---- H phase: K=512, 3 terms, 2 chunks, warp owns 32 k-cols/chunk ----
        #pragma unroll
        for (int c = 0; c < 2; ++c) {
            if (c == 0) cp_wait<1>(); else cp_wait<0>();
            __syncthreads();
            #pragma unroll
            for (int kk = 0; kk < 2; ++kk) {
                const int k = c * 256 + w * 32 + kk * 16;  // fused k (Wl half)
                wmma::fragment<wmma::matrix_a, 16, 16, 16, __half, wmma::row_major> ah[2], al[2];
                wmma::fragment<wmma::matrix_b, 16, 16, 16, __half, wmma::col_major> bh[2], bl[2];
                #pragma unroll
                for (int mi = 0; mi < 2; ++mi) {
                    wmma::load_matrix_sync(ah[mi], &sm.u.Hp[0][mi * 16][k], AS);
                    wmma::load_matrix_sync(al[mi], &sm.u.Hp[1][mi * 16][k], AS);
                }
                #pragma unroll
                for (int ni = 0; ni < 2; ++ni) {
                    wmma::load_matrix_sync(bh[ni], &sm.Wth[ni * 16][k], WKS);
                    wmma::load_matrix_sync(bl[ni], &sm.Wtl[ni * 16][k], WKS);
                }
                #pragma unroll
                for (int mi = 0; mi < 2; ++mi)
                    #pragma unroll
                    for (int ni = 0; ni < 2; ++ni) {
                        wmma::mma_sync(acc[mi][ni], ah[mi], bh[ni], acc[mi][ni]);
                        wmma::mma_sync(acc[mi][ni], ah[mi], bl[ni], acc[mi][ni]);
                        wmma::mma_sync(acc[mi][ni], al[mi], bh[ni], acc[mi][ni]);
                    }
            }
        }
        __syncthreads();                     // H reads done; red overlays Hp

        // ---- reduce 8 warp partials ----
        #pragma unroll
        for (int mi = 0; mi < 2; ++mi)
            #pragma unroll
            for (int ni = 0; ni < 2; ++ni)
                wmma::store_matrix_sync(&sm.u.red[w][mi * 16][ni * 16],
                                        acc[mi][ni], RPAD, wmma::mem_row_major);
        __syncthreads();

        // ---- epilogue: bias + tanh; write fp16 hi/lo planes (or fp32 out) ----
        {
            float4 sum = *(const float4*)&sm.u.red[0][er][ec0];
            #pragma unroll
            for (int p = 1; p < 8; ++p) {
                float4 t = *(const float4*)&sm.u.red[p][er][ec0];
                sum.x += t.x; sum.y += t.y; sum.z += t.z; sum.w += t.w;
            }
            float v0 = fast_tanh(sum.x + bias4.x);
            float v1 = fast_tanh(sum.y + bias4.y);
            float v2 = fast_tanh(sum.z + bias4.z);
            float v3 = fast_tanh(sum.w + bias4.w);

            size_t o = (size_t)(rb + er) * HID + cb + ec0;
            if (s == nsteps) {
                *(float4*)&out[o] = make_float4(v0, v1, v2, v3);
            } else {
                __half h0, l0, h1, l1, h2, l2, h3, l3;
                split_h(v0, h0, l0); split_h(v1, h1, l1);
                split_h(v2, h2, l2); split_h(v3, h3, l3);
                __half2 hh01 = __halves2half2(h0, h1), hh23 = __halves2half2(h2, h3);
                __half2 ll01 = __halves2half2(l0, l1), ll23 = __halves2half2(l2, l3);
                *(uint2*)&g_Hh[s & 1][o] =
                    make_uint2(*(unsigned*)&hh01, *(unsigned*)&hh23);
                *(uint2*)&g_Hl[s & 1][o] =
                    make_uint2(*(unsigned*)&ll01, *(unsigned*)&ll23);
            }
        }

        if (s < nsteps) {
            __syncthreads();                 // all epilogue stores issued
            if (tid == 0) bar_arrive(barp);  // release: our H writes visible
            issue_E(sm);                     // next E flies through the barrier
        }
    }
}

extern "C" void kernel_launch(void* const* d_in, const int* in_sizes, int n_in,
                              void* d_out, int out_size)
{
    const int*   tokens = (const int*)  d_in[0];   // [511, 256]
    const float* emb    = (const float*)d_in[1];   // [32000, 512]
    const float* Wl     = (const float*)d_in[2];   // [512, 512]
    const float* Wr     = (const float*)d_in[3];   // [512, 512]
    const float* bias   = (const float*)d_in[4];   // [512]
    float* out = (float*)d_out;                    // [256, 512]

    const int T      = in_sizes[0] / BATCH;  // 511
    const int nsteps = (T - 1) / 2;          // 255 reduce steps
    const int nemb   = in_sizes[1];          // 32000*512

    cudaFuncSetAttribute(chain_kernel,
                         cudaFuncAttributeMaxDynamicSharedMemorySize,
                         (int)sizeof(SMem));

    prep_emb<<<(nemb / 4 + 255) / 256, 256>>>(emb, nemb);
    init_kernel<<<BATCH, HID / 4>>>(tokens, emb);
    chain_kernel<<<NBLK, 256, sizeof(SMem)>>>(tokens, Wl, Wr, bias, out, nsteps);
}

// round 16
// speedup vs baseline: 1.2567x; 1.0412x over previous
#include <cuda_runtime.h>
#include <cuda_fp16.h>
#include <mma.h>
#include <cstddef>

using namespace nvcuda;

#define BATCH 256
#define HID   512
#define NBLK  128           // 8 row-groups x 16 col-tiles, all co-resident
#define WKS   1032          // W k-major stride (elems): 2064B rows, LDSM conflict-free
#define AS    520           // A row stride (elems): 1040B rows, LDSM conflict-free
#define RPAD  36            // reduction row stride (fp32), float4-aligned

// ---- scratch (static __device__, allocation-free per harness rules) ----
__device__ __half    g_E[32000 * HID];      // embedding, fp16 (unsplit)
__device__ __half    g_Hh[2][BATCH * HID];  // ping-pong hidden state, fp16 hi
__device__ __half    g_Hl[2][BATCH * HID];  // fp16 residual
__device__ unsigned  g_bar[8 * 32];         // per-row-group barrier counters

struct SMem {
    __half Wth[32][WKS];                 // 66048B  W col-slice, k-major, hi
    __half Wtl[32][WKS];                 // 66048B  lo
    __half E[32][AS];                    // 33280B  persistent E buffer
    union {
        __half Hp[2][32][AS];            // 66560B  H hi/lo staging
        float  red[8][32][RPAD];         // 36864B  warp-partial reduction
    } u;
    int stok[32];
};                                        // 232064B total (<= 232448 limit)

// tokens may be int32 (jax default) or int64. tokens[0][1] is a real token
// >= 3, so a zero second 32-bit word means little-endian int64.
__device__ __forceinline__ int load_tok(const int* tokens, long long idx)
{
    if (tokens[1] == 0) return (int)((const long long*)tokens)[idx];
    return tokens[idx];
}

__device__ __forceinline__ void split_h(float x, __half& hi, __half& lo)
{
    hi = __float2half_rn(x);
    lo = __float2half_rn(x - __half2float(hi));
}

// tanh(x) = 1 - 2/(exp2(2x*log2e) + 1); ex2/rcp approx err ~1e-6.
// Saturates correctly: x->+inf: rcp(inf)=0 -> 1; x->-inf: e->0 -> -1.
__device__ __forceinline__ float fast_tanh(float x)
{
    float e;
    asm("ex2.approx.f32 %0, %1;" : "=f"(e) : "f"(x * 2.885390081777927f));
    float r;
    asm("rcp.approx.f32 %0, %1;" : "=f"(r) : "f"(e + 1.0f));
    return fmaf(-2.0f, r, 1.0f);
}

__device__ __forceinline__ void cp_async16(void* dst, const void* src)
{
    unsigned d = (unsigned)__cvta_generic_to_shared(dst);
    asm volatile("cp.async.cg.shared.global [%0], [%1], 16;" :: "r"(d), "l"(src));
}
__device__ __forceinline__ void cp_commit()
{
    asm volatile("cp.async.commit_group;" ::: "memory");
}
template <int N> __device__ __forceinline__ void cp_wait()
{
    asm volatile("cp.async.wait_group %0;" :: "n"(N) : "memory");
}

__device__ __forceinline__ void bar_arrive(unsigned* p)
{
    asm volatile("red.release.gpu.global.add.u32 [%0], %1;"
                 :: "l"(p), "r"(1u) : "memory");
}
__device__ __forceinline__ unsigned bar_peek(const unsigned* p)
{
    unsigned v;
    asm volatile("ld.acquire.gpu.global.u32 %0, [%1];"
                 : "=r"(v) : "l"(p) : "memory");
    return v;
}

// ---- convert the embedding table to fp16 (single plane) ----
__global__ void prep_emb(const float* __restrict__ emb, int n)
{
    int e = (blockIdx.x * blockDim.x + threadIdx.x) * 4;
    if (e >= n) return;
    float4 v = __ldcs((const float4*)(emb + e));
    __half2 p01 = __floats2half2_rn(v.x, v.y);
    __half2 p23 = __floats2half2_rn(v.z, v.w);
    __stcs((uint2*)&g_E[e], make_uint2(*(unsigned*)&p01, *(unsigned*)&p23));
}

// ---- h0 = emb[tok0] split to fp16 hi/lo ; reset barrier counters ----
__global__ void init_kernel(const int* __restrict__ tokens,
                            const float* __restrict__ emb)
{
    if (blockIdx.x == 0 && threadIdx.x < 8) g_bar[threadIdx.x * 32] = 0u;
    int b = blockIdx.x;
    long long tok = load_tok(tokens, b);
    int c = threadIdx.x * 4;                    // 128 threads x 4 cols
    float4 v = *(const float4*)(emb + tok * HID + c);
    __half h[4], l[4];
    split_h(v.x, h[0], l[0]); split_h(v.y, h[1], l[1]);
    split_h(v.z, h[2], l[2]); split_h(v.w, h[3], l[3]);
    __half2 hh01 = __halves2half2(h[0], h[1]), hh23 = __halves2half2(h[2], h[3]);
    __half2 ll01 = __halves2half2(l[0], l[1]), ll23 = __halves2half2(l[2], l[3]);
    size_t o = (size_t)b * HID + c;
    *(uint2*)&g_Hh[0][o] = make_uint2(*(unsigned*)&hh01, *(unsigned*)&hh23);
    *(uint2*)&g_Hl[0][o] = make_uint2(*(unsigned*)&ll01, *(unsigned*)&ll23);
}

// issue cp.async: whole E tile (32 rows x 512) into the persistent E buffer
__device__ __forceinline__ void issue_E(SMem& sm)
{
    const int t   = threadIdx.x;
    const int row = t >> 3;
    const int seg = (t & 7) * 64;
    const __half* src = g_E + (size_t)sm.stok[row] * HID + seg;
    __half* dst = &sm.E[row][seg];
    #pragma unroll
    for (int i = 0; i < 8; ++i) cp_async16(dst + i * 8, src + i * 8);
    cp_commit();
}

// issue cp.async: H chunk c (k in [c*256, c*256+256)), hi+lo planes
__device__ __forceinline__ void issue_Hc(SMem& sm, int c, int s, int rb)
{
    const int t   = threadIdx.x;
    const int row = t >> 3;
    const int kb  = c * 256 + (t & 7) * 32;
    size_t o = (size_t)(rb + row) * HID + kb;
    const __half* sh = g_Hh[(s - 1) & 1] + o;
    const __half* sl = g_Hl[(s - 1) & 1] + o;
    #pragma unroll
    for (int i = 0; i < 4; ++i) {
        cp_async16(&sm.u.Hp[0][row][kb + i * 8], sh + i * 8);
        cp_async16(&sm.u.Hp[1][row][kb + i * 8], sl + i * 8);
    }
    cp_commit();
}

// one H-phase k-step: 3 terms (HhWh + HhWl + HlWh) at fused k
__device__ __forceinline__ void mma_H(SMem& sm, int k,
    wmma::fragment<wmma::accumulator, 16, 16, 16, float> (&acc)[2][2])
{
    wmma::fragment<wmma::matrix_a, 16, 16, 16, __half, wmma::row_major> ah[2], al[2];
    wmma::fragment<wmma::matrix_b, 16, 16, 16, __half, wmma::col_major> bh[2], bl[2];
    #pragma unroll
    for (int mi = 0; mi < 2; ++mi) {
        wmma::load_matrix_sync(ah[mi], &sm.u.Hp[0][mi * 16][k], AS);
        wmma::load_matrix_sync(al[mi], &sm.u.Hp[1][mi * 16][k], AS);
    }
    #pragma unroll
    for (int ni = 0; ni < 2; ++ni) {
        wmma::load_matrix_sync(bh[ni], &sm.Wth[ni * 16][k], WKS);
        wmma::load_matrix_sync(bl[ni], &sm.Wtl[ni * 16][k], WKS);
    }
    #pragma unroll
    for (int mi = 0; mi < 2; ++mi)
        #pragma unroll
        for (int ni = 0; ni < 2; ++ni) {
            wmma::mma_sync(acc[mi][ni], ah[mi], bh[ni], acc[mi][ni]);
            wmma::mma_sync(acc[mi][ni], ah[mi], bl[ni], acc[mi][ni]);
            wmma::mma_sync(acc[mi][ni], al[mi], bh[ni], acc[mi][ni]);
        }
}

// Persistent chain kernel: 255 reduce steps, one launch.
// Block = 32x32 output tile; 8 warps split K. Per step:
//   E phase: K=512, single term E@Wh (W-residual error folds into the
//            existing 2^-12 E-quant error budget, quadrature-added)
//   H phase: K=512, H split fp16 hi/lo -> 3 terms (HhWh + HhWl + HlWh)
// W slice (k-major, fp16 hi/lo) resident in smem for the whole kernel.
// Speculative H staging: if the inter-block barrier is already satisfied at
// the top of the step (acquire-peek BEFORE issue, uniform via
// __syncthreads_and), H cp.asyncs issue immediately and their flight hides
// under the E-phase MMAs; the H phase then needs only one wait+sync.
// Otherwise: proven R11 slow path (E-mma -> spin -> sync -> issue -> chunked).
__global__ void __launch_bounds__(256, 1)
chain_kernel(const int* __restrict__ tokens,
             const float* __restrict__ Wl,
             const float* __restrict__ Wr,
             const float* __restrict__ bias,
             float* __restrict__ out,
             int nsteps)
{
    extern __shared__ char smem_raw[];
    SMem& sm = *reinterpret_cast<SMem*>(smem_raw);

    const int tid = threadIdx.x;
    const int w   = tid >> 5;
    const int rg  = blockIdx.x >> 4;        // row group 0..7 (independent chains)
    const int rb  = rg * 32;
    const int cb  = (blockIdx.x & 15) * 32;
    unsigned* barp = &g_bar[rg * 32];

    // ---- one-time: load + split W col slice into k-major smem planes ----
    {
        const int col = tid & 31;
        const int kr  = tid >> 5;            // 8 k-rows per iter
        for (int it = 0; it < 128; ++it) {
            int k = it * 8 + kr;             // 0..1023 over [Wl ; Wr]
            float v = (k < HID) ? Wl[(size_t)k * HID + cb + col]
                                : Wr[(size_t)(k - HID) * HID + cb + col];
            __half h, l;
            split_h(v, h, l);
            sm.Wth[col][k] = h;
            sm.Wtl[col][k] = l;
        }
    }

    // epilogue role + cached bias
    const int er  = tid >> 3;
    const int ec0 = (tid & 7) * 4;
    const float4 bias4 = *(const float4*)(bias + cb + ec0);

    // prologue: step-1 tokens, then prefetch step-1 E
    if (tid < 32) sm.stok[tid] = load_tok(tokens, (long long)BATCH + rb + tid);
    __syncthreads();
    issue_E(sm);

    for (int s = 1; s <= nsteps; ++s) {
        // prefetch next step's tokens (off critical path; tokens L1-resident)
        int treg = 0;
        if (tid < 32 && s < nsteps)
            treg = load_tok(tokens, (long long)(2 * s + 1) * BATCH + rb + tid);

        wmma::fragment<wmma::accumulator, 16, 16, 16, float> acc[2][2];
        #pragma unroll
        for (int mi = 0; mi < 2; ++mi)
            #pragma unroll
            for (int ni = 0; ni < 2; ++ni)
                wmma::fill_fragment(acc[mi][ni], 0.0f);

        // ---- E staged? (issued at previous step's tail / prologue) ----
        cp_wait<0>();
        __syncthreads();

        // publish next step's tokens: E(s) cp.async already captured its
        // addresses; multiple syncs separate this from the tail's issue_E
        if (tid < 32 && s < nsteps) sm.stok[tid] = treg;

        // ---- speculative barrier check (uniform; acquire BEFORE issue) ----
        const unsigned target = 16u * (unsigned)(s - 1);
        int pred = (s == 1) || (bar_peek(barp) >= target);
        int fast = __syncthreads_and(pred);
        if (fast) {                          // peers' H already visible:
            issue_Hc(sm, 0, s, rb);          //   stage now; flight hides
            issue_Hc(sm, 1, s, rb);          //   under the E-phase MMAs
        }

        // ---- E phase: K=512, single term E@Wh, warp owns 64 k-cols ----
        #pragma unroll
        for (int kk = 0; kk < 4; ++kk) {
            const int kl = w * 64 + kk * 16;       // within E's K
            const int kf = HID + kl;               // fused k (Wr half)
            wmma::fragment<wmma::matrix_a, 16, 16, 16, __half, wmma::row_major> ah[2];
            wmma::fragment<wmma::matrix_b, 16, 16, 16, __half, wmma::col_major> bh[2];
            #pragma unroll
            for (int mi = 0; mi < 2; ++mi)
                wmma::load_matrix_sync(ah[mi], &sm.E[mi * 16][kl], AS);
            #pragma unroll
            for (int ni = 0; ni < 2; ++ni)
                wmma::load_matrix_sync(bh[ni], &sm.Wth[ni * 16][kf], WKS);
            #pragma unroll
            for (int mi = 0; mi < 2; ++mi)
                #pragma unroll
                for (int ni = 0; ni < 2; ++ni)
                    wmma::mma_sync(acc[mi][ni], ah[mi], bh[ni], acc[mi][ni]);
        }

        // ---- H phase ----
        if (fast) {
            // both chunks already (nearly) resident: one wait, one sync
            cp_wait<0>();
            __syncthreads();
            #pragma unroll
            for (int c = 0; c < 2; ++c)
                #pragma unroll
                for (int kk = 0; kk < 2; ++kk)
                    mma_H(sm, c * 256 + w * 32 + kk * 16, acc);
        } else {
            // slow path: spin, then chunked issue/compute (R11 protocol)
            if (tid == 0) {
                while (bar_peek(barp) < target) { }
            }
            __syncthreads();
            issue_Hc(sm, 0, s, rb);
            issue_Hc(sm, 1, s, rb);
            #pragma unroll
            for (int c = 0; c < 2; ++c) {
                if (c == 0) cp_wait<1>(); else cp_wait<0>();
                __syncthreads();
                #pragma unroll
                for (int kk = 0; kk < 2; ++kk)
                    mma_H(sm, c * 256 + w * 32 + kk * 16, acc);
            }
        }
        __syncthreads();                     // H reads done; red overlays Hp

        // ---- reduce 8 warp partials ----
        #pragma unroll
        for (int mi = 0; mi < 2; ++mi)
            #pragma unroll
            for (int ni = 0; ni < 2; ++ni)
                wmma::store_matrix_sync(&sm.u.red[w][mi * 16][ni * 16],
                                        acc[mi][ni], RPAD, wmma::mem_row_major);
        __syncthreads();

        // ---- epilogue: bias + tanh; write fp16 hi/lo planes (or fp32 out) ----
        {
            float4 sum = *(const float4*)&sm.u.red[0][er][ec0];
            #pragma unroll
            for (int p = 1; p < 8; ++p) {
                float4 t = *(const float4*)&sm.u.red[p][er][ec0];
                sum.x += t.x; sum.y += t.y; sum.z += t.z; sum.w += t.w;
            }
            float v0 = fast_tanh(sum.x + bias4.x);
            float v1 = fast_tanh(sum.y + bias4.y);
            float v2 = fast_tanh(sum.z + bias4.z);
            float v3 = fast_tanh(sum.w + bias4.w);

            size_t o = (size_t)(rb + er) * HID + cb + ec0;
            if (s == nsteps) {
                *(float4*)&out[o] = make_float4(v0, v1, v2, v3);
            } else {
                __half h0, l0, h1, l1, h2, l2, h3, l3;
                split_h(v0, h0, l0); split_h(v1, h1, l1);
                split_h(v2, h2, l2); split_h(v3, h3, l3);
                __half2 hh01 = __halves2half2(h0, h1), hh23 = __halves2half2(h2, h3);
                __half2 ll01 = __halves2half2(l0, l1), ll23 = __halves2half2(l2, l3);
                *(uint2*)&g_Hh[s & 1][o] =
                    make_uint2(*(unsigned*)&hh01, *(unsigned*)&hh23);
                *(uint2*)&g_Hl[s & 1][o] =
                    make_uint2(*(unsigned*)&ll01, *(unsigned*)&ll23);
            }
        }

        if (s < nsteps) {
            __syncthreads();                 // all epilogue stores issued
            if (tid == 0) bar_arrive(barp);  // release: our H writes visible
            issue_E(sm);                     // next E flies through the barrier
        }
    }
}

extern "C" void kernel_launch(void* const* d_in, const int* in_sizes, int n_in,
                              void* d_out, int out_size)
{
    const int*   tokens = (const int*)  d_in[0];   // [511, 256]
    const float* emb    = (const float*)d_in[1];   // [32000, 512]
    const float* Wl     = (const float*)d_in[2];   // [512, 512]
    const float* Wr     = (const float*)d_in[3];   // [512, 512]
    const float* bias   = (const float*)d_in[4];   // [512]
    float* out = (float*)d_out;                    // [256, 512]

    const int T      = in_sizes[0] / BATCH;  // 511
    const int nsteps = (T - 1) / 2;          // 255 reduce steps
    const int nemb   = in_sizes[1];          // 32000*512

    cudaFuncSetAttribute(chain_kernel,
                         cudaFuncAttributeMaxDynamicSharedMemorySize,
                         (int)sizeof(SMem));

    prep_emb<<<(nemb / 4 + 255) / 256, 256>>>(emb, nemb);
    init_kernel<<<BATCH, HID / 4>>>(tokens, emb);
    chain_kernel<<<NBLK, 256, sizeof(SMem)>>>(tokens, Wl, Wr, bias, out, nsteps);
}